// round 2
// baseline (speedup 1.0000x reference)
#include <cuda_runtime.h>
#include <math.h>

// Problem constants
#define BB   2
#define NN   2048
#define DD   2048
#define HH   16
#define HKV  4
#define HD   128
#define GG   (HH / HKV)     // 4
#define SCALE 0.08838834764831845f   // 1/sqrt(128)

// ---------------------------------------------------------------------------
// Device scratch (allocation-free: __device__ globals)
// ---------------------------------------------------------------------------
__device__ float g_Q  [(size_t)BB * NN * HH * HD];            // [b][n][h][hd]   32 MB
__device__ float g_KV [(size_t)BB * NN * 2 * HKV * HD];       // [b][n][2*HKV*HD] 16 MB
__device__ float g_S  [(size_t)BB * HH * NN * NN];            // [b*H+h][n][m]   512 MB
__device__ float g_ctx[(size_t)BB * NN * HH * HD];            // [b][n][h][hd]   32 MB

// ---------------------------------------------------------------------------
// Generic fp32 SGEMM (NN): C[M,Nc] = A[M,K] @ B[K,Nc] (+ bias[Nc])
// 128x128 block tile, BK=8, 256 threads, 8x8 per thread.
// ---------------------------------------------------------------------------
__global__ __launch_bounds__(256) void sgemm_nn(
    const float* __restrict__ A, int lda,
    const float* __restrict__ B, int ldb,
    float* __restrict__ C, int ldc,
    int K, const float* __restrict__ bias)
{
    __shared__ __align__(16) float As[8][128];
    __shared__ __align__(16) float Bs[8][128];

    const int t  = threadIdx.x;
    const int tx = t & 15;
    const int ty = t >> 4;
    const int m0 = blockIdx.y * 128;
    const int n0 = blockIdx.x * 128;

    const int arow = t >> 1;
    const int acol = (t & 1) * 4;
    const int brow = t >> 5;
    const int bcol = (t & 31) * 4;

    float acc[8][8];
    #pragma unroll
    for (int i = 0; i < 8; i++)
        #pragma unroll
        for (int j = 0; j < 8; j++) acc[i][j] = 0.f;

    for (int k0 = 0; k0 < K; k0 += 8) {
        float4 av = *(const float4*)(A + (size_t)(m0 + arow) * lda + k0 + acol);
        float4 bv = *(const float4*)(B + (size_t)(k0 + brow) * ldb + n0 + bcol);
        As[acol + 0][arow] = av.x;
        As[acol + 1][arow] = av.y;
        As[acol + 2][arow] = av.z;
        As[acol + 3][arow] = av.w;
        *(float4*)&Bs[brow][bcol] = bv;
        __syncthreads();

        #pragma unroll
        for (int kk = 0; kk < 8; kk++) {
            float a[8], b[8];
            #pragma unroll
            for (int i = 0; i < 8; i++) a[i] = As[kk][ty * 8 + i];
            #pragma unroll
            for (int j = 0; j < 8; j++) b[j] = Bs[kk][tx * 8 + j];
            #pragma unroll
            for (int i = 0; i < 8; i++)
                #pragma unroll
                for (int j = 0; j < 8; j++) acc[i][j] += a[i] * b[j];
        }
        __syncthreads();
    }

    #pragma unroll
    for (int i = 0; i < 8; i++) {
        const int row = m0 + ty * 8 + i;
        float* cp = C + (size_t)row * ldc + n0 + tx * 8;
        #pragma unroll
        for (int j = 0; j < 8; j++) {
            float v = acc[i][j];
            if (bias) v += bias[n0 + tx * 8 + j];
            cp[j] = v;
        }
    }
}

// ---------------------------------------------------------------------------
// RoPE in-place on g_Q and K-part of g_KV.  cos/sin: [N, 64]
// ---------------------------------------------------------------------------
__global__ void rope_kernel(const float* __restrict__ cosb,
                            const float* __restrict__ sinb)
{
    int idx = blockIdx.x * blockDim.x + threadIdx.x;
    const int NQ = BB * NN * HH * (HD / 2);
    const int NK = BB * NN * HKV * (HD / 2);
    if (idx < NQ) {
        int i  = idx & 63;
        int h  = (idx >> 6) % HH;
        int bn = idx / (64 * HH);           // b*N + n
        int n  = bn % NN;
        float c = cosb[n * 64 + i], s = sinb[n * 64 + i];
        float* q = g_Q + ((size_t)bn * HH + h) * HD;
        float t1 = q[i], t2 = q[i + 64];
        q[i]      = t1 * c + t2 * s;
        q[i + 64] = t2 * c - t1 * s;
    } else {
        idx -= NQ;
        if (idx < NK) {
            int i  = idx & 63;
            int hk = (idx >> 6) % HKV;
            int bn = idx / (64 * HKV);
            int n  = bn % NN;
            float c = cosb[n * 64 + i], s = sinb[n * 64 + i];
            float* k = g_KV + (size_t)bn * (2 * HKV * HD) + hk * HD;
            float t1 = k[i], t2 = k[i + 64];
            k[i]      = t1 * c + t2 * s;
            k[i + 64] = t2 * c - t1 * s;
        }
    }
}

// ---------------------------------------------------------------------------
// Scores: S[z=b*H+h] = Q_h @ K_hkv^T * scale + (1-mask)*-1e9
// Reference reshape (b,G,HKV,n,HD) => query head h pairs with kv head h % HKV.
// ---------------------------------------------------------------------------
__global__ __launch_bounds__(256) void attn_scores(const float* __restrict__ mask)
{
    __shared__ __align__(16) float As[8][128];
    __shared__ __align__(16) float Bs[8][128];

    const int z   = blockIdx.z;
    const int b   = z / HH;
    const int h   = z % HH;
    const int hkv = h % HKV;          // FIXED: reference splits h = g*HKV + hkv

    const float* A  = g_Q + ((size_t)b * NN * HH + h) * HD;
    const float* Bk = g_KV + (size_t)b * NN * (2 * HKV * HD) + hkv * HD;
    float* C = g_S + (size_t)z * NN * NN;
    const int lda = HH * HD;        // 2048
    const int ldb = 2 * HKV * HD;   // 1024

    const int t  = threadIdx.x;
    const int tx = t & 15, ty = t >> 4;
    const int m0 = blockIdx.y * 128;
    const int n0 = blockIdx.x * 128;

    const int arow = t >> 1;
    const int acol = (t & 1) * 4;

    float acc[8][8];
    #pragma unroll
    for (int i = 0; i < 8; i++)
        #pragma unroll
        for (int j = 0; j < 8; j++) acc[i][j] = 0.f;

    for (int k0 = 0; k0 < HD; k0 += 8) {
        float4 av = *(const float4*)(A  + (size_t)(m0 + arow) * lda + k0 + acol);
        float4 bv = *(const float4*)(Bk + (size_t)(n0 + arow) * ldb + k0 + acol);
        As[acol + 0][arow] = av.x; As[acol + 1][arow] = av.y;
        As[acol + 2][arow] = av.z; As[acol + 3][arow] = av.w;
        Bs[acol + 0][arow] = bv.x; Bs[acol + 1][arow] = bv.y;
        Bs[acol + 2][arow] = bv.z; Bs[acol + 3][arow] = bv.w;
        __syncthreads();

        #pragma unroll
        for (int kk = 0; kk < 8; kk++) {
            float a[8], bb[8];
            #pragma unroll
            for (int i = 0; i < 8; i++) a[i]  = As[kk][ty * 8 + i];
            #pragma unroll
            for (int j = 0; j < 8; j++) bb[j] = Bs[kk][tx * 8 + j];
            #pragma unroll
            for (int i = 0; i < 8; i++)
                #pragma unroll
                for (int j = 0; j < 8; j++) acc[i][j] += a[i] * bb[j];
        }
        __syncthreads();
    }

    #pragma unroll
    for (int i = 0; i < 8; i++) {
        const int row = m0 + ty * 8 + i;
        float* cp = C + (size_t)row * NN + n0 + tx * 8;
        #pragma unroll
        for (int j = 0; j < 8; j++) {
            const int col = n0 + tx * 8 + j;
            float bias = (1.0f - mask[b * NN + col]) * -1e9f;
            cp[j] = acc[i][j] * SCALE + bias;
        }
    }
}

// ---------------------------------------------------------------------------
// Row softmax in-place on g_S. One block (256 thr) per row of 2048.
// ---------------------------------------------------------------------------
__global__ __launch_bounds__(256) void softmax_rows()
{
    __shared__ float red[256];
    float* p = g_S + (size_t)blockIdx.x * NN;
    const int t = threadIdx.x;

    float v[8];
    float m = -INFINITY;
    #pragma unroll
    for (int i = 0; i < 8; i++) { v[i] = p[t + i * 256]; m = fmaxf(m, v[i]); }
    red[t] = m; __syncthreads();
    for (int s = 128; s > 0; s >>= 1) {
        if (t < s) red[t] = fmaxf(red[t], red[t + s]);
        __syncthreads();
    }
    m = red[0]; __syncthreads();

    float sum = 0.f;
    #pragma unroll
    for (int i = 0; i < 8; i++) { v[i] = expf(v[i] - m); sum += v[i]; }
    red[t] = sum; __syncthreads();
    for (int s = 128; s > 0; s >>= 1) {
        if (t < s) red[t] += red[t + s];
        __syncthreads();
    }
    float inv = 1.0f / red[0];
    #pragma unroll
    for (int i = 0; i < 8; i++) p[t + i * 256] = v[i] * inv;
}

// ---------------------------------------------------------------------------
// PV: ctx[b][n][h][:] = P[z] @ V_hkv.  (same hkv = h % HKV fix)
// ---------------------------------------------------------------------------
__global__ __launch_bounds__(256) void attn_pv()
{
    __shared__ __align__(16) float As[8][128];
    __shared__ __align__(16) float Bs[8][128];

    const int z   = blockIdx.z;
    const int b   = z / HH;
    const int h   = z % HH;
    const int hkv = h % HKV;          // FIXED

    const float* A  = g_S + (size_t)z * NN * NN;
    const float* Bp = g_KV + (size_t)b * NN * (2 * HKV * HD) + HKV * HD + hkv * HD;
    float* C = g_ctx + ((size_t)b * NN * HH + h) * HD;
    const int lda = NN, ldb = 2 * HKV * HD, ldc = HH * HD;

    const int t  = threadIdx.x;
    const int tx = t & 15, ty = t >> 4;
    const int m0 = blockIdx.y * 128;

    const int arow = t >> 1;
    const int acol = (t & 1) * 4;
    const int brow = t >> 5;
    const int bcol = (t & 31) * 4;

    float acc[8][8];
    #pragma unroll
    for (int i = 0; i < 8; i++)
        #pragma unroll
        for (int j = 0; j < 8; j++) acc[i][j] = 0.f;

    for (int k0 = 0; k0 < NN; k0 += 8) {
        float4 av = *(const float4*)(A  + (size_t)(m0 + arow) * lda + k0 + acol);
        float4 bv = *(const float4*)(Bp + (size_t)(k0 + brow) * ldb + bcol);
        As[acol + 0][arow] = av.x; As[acol + 1][arow] = av.y;
        As[acol + 2][arow] = av.z; As[acol + 3][arow] = av.w;
        *(float4*)&Bs[brow][bcol] = bv;
        __syncthreads();

        #pragma unroll
        for (int kk = 0; kk < 8; kk++) {
            float a[8], bb[8];
            #pragma unroll
            for (int i = 0; i < 8; i++) a[i]  = As[kk][ty * 8 + i];
            #pragma unroll
            for (int j = 0; j < 8; j++) bb[j] = Bs[kk][tx * 8 + j];
            #pragma unroll
            for (int i = 0; i < 8; i++)
                #pragma unroll
                for (int j = 0; j < 8; j++) acc[i][j] += a[i] * bb[j];
        }
        __syncthreads();
    }

    #pragma unroll
    for (int i = 0; i < 8; i++) {
        const int row = m0 + ty * 8 + i;
        float* cp = C + (size_t)row * ldc + tx * 8;
        #pragma unroll
        for (int j = 0; j < 8; j++) cp[j] = acc[i][j];
    }
}

// ---------------------------------------------------------------------------
// Launch
// ---------------------------------------------------------------------------
extern "C" void kernel_launch(void* const* d_in, const int* in_sizes, int n_in,
                              void* d_out, int out_size)
{
    (void)in_sizes; (void)n_in; (void)out_size;

    const float* x    = (const float*)d_in[0];
    const float* cosb = (const float*)d_in[1];
    const float* sinb = (const float*)d_in[2];
    const float* mask = (const float*)d_in[3];
    const float* Wq   = (const float*)d_in[4];
    const float* Wkv  = (const float*)d_in[5];
    const float* Wo   = (const float*)d_in[6];
    const float* bo   = (const float*)d_in[7];
    float* out = (float*)d_out;

    float *pQ, *pKV, *pCtx;
    cudaGetSymbolAddress((void**)&pQ,   g_Q);
    cudaGetSymbolAddress((void**)&pKV,  g_KV);
    cudaGetSymbolAddress((void**)&pCtx, g_ctx);

    const int M = BB * NN;   // 4096

    // Q = x @ Wq  : [4096,2048] @ [2048,2048]
    sgemm_nn<<<dim3(DD / 128, M / 128), 256>>>(x, DD, Wq, HH * HD, pQ, HH * HD, DD, nullptr);
    // KV = x @ Wkv : [4096,2048] @ [2048,1024]
    sgemm_nn<<<dim3((2 * HKV * HD) / 128, M / 128), 256>>>(x, DD, Wkv, 2 * HKV * HD, pKV, 2 * HKV * HD, DD, nullptr);

    // RoPE on Q and K
    {
        int total = BB * NN * HH * (HD / 2) + BB * NN * HKV * (HD / 2);
        rope_kernel<<<(total + 255) / 256, 256>>>(cosb, sinb);
    }

    // S = Q K^T * scale + bias
    attn_scores<<<dim3(NN / 128, NN / 128, BB * HH), 256>>>(mask);

    // softmax
    softmax_rows<<<BB * HH * NN, 256>>>();

    // ctx = P V
    attn_pv<<<dim3(1, NN / 128, BB * HH), 256>>>();

    // out = ctx @ Wo + bo : [4096,2048] @ [2048,2048]
    sgemm_nn<<<dim3(DD / 128, M / 128), 256>>>(pCtx, HH * HD, Wo, DD, out, DD, DD, bo);
}

// round 4
// speedup vs baseline: 2.3661x; 2.3661x over previous
#include <cuda_runtime.h>
#include <cuda_bf16.h>
#include <math.h>
#include <cstdint>

// ---------------------------------------------------------------------------
// Problem constants
// ---------------------------------------------------------------------------
#define BB   2
#define NN   2048
#define DD   2048
#define HH   16
#define HKV  4
#define HD   128
#define GG   (HH / HKV)
#define QKVW (HH * HD + 2 * HKV * HD)     // 3072: Q(2048) | K(512) | V(512)
#define KOFF (HH * HD)                    // 2048
#define VOFF (HH * HD + HKV * HD)         // 2560
#define SCALE 0.08838834764831845f

#define BK 32                 // K-chunk (fp32 elements)
#define TSTR 80               // smem row stride bytes (64 data + 16 pad)
#define TILE_B (128 * TSTR)   // 10240 bytes per tile
// smem tiles: Ahi | Alo | Bhi | Blo
#define OFF_AHI 0
#define OFF_ALO (TILE_B)
#define OFF_BHI (2 * TILE_B)
#define OFF_BLO (3 * TILE_B)

// ---------------------------------------------------------------------------
// Device scratch (__device__ globals — allocation-free)
// ---------------------------------------------------------------------------
__device__ float g_QKV[(size_t)BB * NN * QKVW];            // 48 MB
__device__ float g_WT [(size_t)QKVW * DD];                 // 24 MB
__device__ float g_WoT[(size_t)DD * DD];                   // 16 MB
__device__ float g_S  [(size_t)BB * HH * NN * NN];         // 512 MB
__device__ float g_Vt [(size_t)BB * HKV * HD * NN];        // 8 MB   [b][hkv][hd][n]
__device__ float g_ctx[(size_t)BB * NN * HH * HD];         // 32 MB

// ---------------------------------------------------------------------------
// PTX helpers (portable sm_80+ tensor path: ldmatrix + mma.sync bf16)
// ---------------------------------------------------------------------------
__device__ __forceinline__ uint32_t smem_u32(const void* p) {
    uint32_t a;
    asm("{ .reg .u64 t; cvta.to.shared.u64 t, %1; cvt.u32.u64 %0, t; }" : "=r"(a) : "l"(p));
    return a;
}
__device__ __forceinline__ void ldmx4(uint32_t& r0, uint32_t& r1, uint32_t& r2, uint32_t& r3, uint32_t addr) {
    asm volatile("ldmatrix.sync.aligned.m8n8.x4.shared.b16 {%0,%1,%2,%3}, [%4];"
                 : "=r"(r0), "=r"(r1), "=r"(r2), "=r"(r3) : "r"(addr));
}
__device__ __forceinline__ void mma16816(float* c, const uint32_t* a, const uint32_t* b) {
    asm volatile(
        "mma.sync.aligned.m16n8k16.row.col.f32.bf16.bf16.f32 "
        "{%0,%1,%2,%3}, {%4,%5,%6,%7}, {%8,%9}, {%0,%1,%2,%3};"
        : "+f"(c[0]), "+f"(c[1]), "+f"(c[2]), "+f"(c[3])
        : "r"(a[0]), "r"(a[1]), "r"(a[2]), "r"(a[3]), "r"(b[0]), "r"(b[1]));
}

__device__ __forceinline__ void split4(float4 v, uint2& hi, uint2& lo) {
    __nv_bfloat16 hx = __float2bfloat16(v.x), hy = __float2bfloat16(v.y),
                  hz = __float2bfloat16(v.z), hw = __float2bfloat16(v.w);
    __nv_bfloat162 h01 = __halves2bfloat162(hx, hy), h23 = __halves2bfloat162(hz, hw);
    __nv_bfloat16 lx = __float2bfloat16(v.x - __bfloat162float(hx));
    __nv_bfloat16 ly = __float2bfloat16(v.y - __bfloat162float(hy));
    __nv_bfloat16 lz = __float2bfloat16(v.z - __bfloat162float(hz));
    __nv_bfloat16 lw = __float2bfloat16(v.w - __bfloat162float(hw));
    __nv_bfloat162 l01 = __halves2bfloat162(lx, ly), l23 = __halves2bfloat162(lz, lw);
    hi = make_uint2(*(uint32_t*)&h01, *(uint32_t*)&h23);
    lo = make_uint2(*(uint32_t*)&l01, *(uint32_t*)&l23);
}

// ---------------------------------------------------------------------------
// Mainloop: acc[2][8][4] += A[128,K] @ B[128,K]^T  (bf16 hi/lo split, fp32 acc)
// 256 threads; warp layout 4(M) x 2(N); warp tile 32x64.
// ---------------------------------------------------------------------------
__device__ __forceinline__ void mma_mainloop(
    const float* __restrict__ A, int lda,
    const float* __restrict__ B, int ldb, int K,
    float c[2][8][4])
{
    __shared__ __align__(16) char smem[4 * TILE_B];   // 40960 B

    const int t    = threadIdx.x;
    const int lane = t & 31;
    const int warp = t >> 5;
    const int wm   = warp >> 1;   // 0..3
    const int wn   = warp & 1;    // 0..1
    const uint32_t sm = smem_u32(smem);

    // fragment base addresses
    const uint32_t a_ad = sm + (uint32_t)((wm * 32 + (lane & 15)) * TSTR + (lane >> 4) * 16);
    const uint32_t b_ad = sm + OFF_BHI +
        (uint32_t)((wn * 64 + ((lane >> 4) * 8) + (lane & 7)) * TSTR + ((lane >> 3) & 1) * 16);

    // loader indices: idx = t + i*256; row = idx>>3; c4 = idx&7 (8 float4 per 32-float row)
    float4 pa[4], pb[4];
    const int nch = K / BK;

    // prefetch chunk 0
    #pragma unroll
    for (int i = 0; i < 4; ++i) {
        int idx = t + i * 256, row = idx >> 3, c4 = idx & 7;
        pa[i] = *(const float4*)(A + (size_t)row * lda + c4 * 4);
        pb[i] = *(const float4*)(B + (size_t)row * ldb + c4 * 4);
    }

    for (int ch = 0; ch < nch; ++ch) {
        __syncthreads();   // previous compute must finish before overwrite
        #pragma unroll
        for (int i = 0; i < 4; ++i) {
            int idx = t + i * 256, row = idx >> 3, c4 = idx & 7;
            uint32_t off = (uint32_t)(row * TSTR + c4 * 8);
            uint2 hi, lo;
            split4(pa[i], hi, lo);
            *(uint2*)(smem + OFF_AHI + off) = hi;
            *(uint2*)(smem + OFF_ALO + off) = lo;
            split4(pb[i], hi, lo);
            *(uint2*)(smem + OFF_BHI + off) = hi;
            *(uint2*)(smem + OFF_BLO + off) = lo;
        }
        __syncthreads();

        if (ch + 1 < nch) {
            const int k0 = (ch + 1) * BK;
            #pragma unroll
            for (int i = 0; i < 4; ++i) {
                int idx = t + i * 256, row = idx >> 3, c4 = idx & 7;
                pa[i] = *(const float4*)(A + (size_t)row * lda + k0 + c4 * 4);
                pb[i] = *(const float4*)(B + (size_t)row * ldb + k0 + c4 * 4);
            }
        }

        #pragma unroll
        for (int ks = 0; ks < 2; ++ks) {
            uint32_t ah[2][4], al[2][4], bh[8][2], bl[8][2];
            #pragma unroll
            for (int mt = 0; mt < 2; ++mt) {
                uint32_t ad = a_ad + (uint32_t)(mt * 16 * TSTR + ks * 32);
                ldmx4(ah[mt][0], ah[mt][1], ah[mt][2], ah[mt][3], ad + OFF_AHI);
                ldmx4(al[mt][0], al[mt][1], al[mt][2], al[mt][3], ad + OFF_ALO);
            }
            #pragma unroll
            for (int np = 0; np < 4; ++np) {
                uint32_t ad = b_ad + (uint32_t)(np * 16 * TSTR + ks * 32);
                ldmx4(bh[np * 2][0], bh[np * 2][1], bh[np * 2 + 1][0], bh[np * 2 + 1][1], ad);
                ldmx4(bl[np * 2][0], bl[np * 2][1], bl[np * 2 + 1][0], bl[np * 2 + 1][1], ad + TILE_B);
            }
            #pragma unroll
            for (int mt = 0; mt < 2; ++mt)
                #pragma unroll
                for (int nt = 0; nt < 8; ++nt) {
                    mma16816(c[mt][nt], ah[mt], bh[nt]);
                    mma16816(c[mt][nt], ah[mt], bl[nt]);
                    mma16816(c[mt][nt], al[mt], bh[nt]);
                }
        }
    }
}

// ---------------------------------------------------------------------------
// Generic NT GEMM: C[m0+i][n0+j] = sum_k A[m0+i][k]*B[n0+j][k] (+bias)
// ---------------------------------------------------------------------------
__global__ __launch_bounds__(256) void gemm_nt_mma(
    const float* __restrict__ A, int lda,
    const float* __restrict__ B, int ldb,
    float* __restrict__ C, int ldc, int K,
    const float* __restrict__ bias)
{
    const int m0 = blockIdx.y * 128, n0 = blockIdx.x * 128;
    float c[2][8][4];
    #pragma unroll
    for (int mt = 0; mt < 2; ++mt)
        #pragma unroll
        for (int nt = 0; nt < 8; ++nt)
            #pragma unroll
            for (int i = 0; i < 4; ++i) c[mt][nt][i] = 0.f;

    mma_mainloop(A + (size_t)m0 * lda, lda, B + (size_t)n0 * ldb, ldb, K, c);

    const int lane = threadIdx.x & 31, warp = threadIdx.x >> 5;
    const int rb = m0 + (warp >> 1) * 32 + (lane >> 2);
    const int cb = n0 + (warp & 1) * 64 + (lane & 3) * 2;
    #pragma unroll
    for (int mt = 0; mt < 2; ++mt)
        #pragma unroll
        for (int nt = 0; nt < 8; ++nt) {
            int row = rb + mt * 16, col = cb + nt * 8;
            float b0 = bias ? bias[col] : 0.f, b1 = bias ? bias[col + 1] : 0.f;
            *(float2*)(C + (size_t)row * ldc + col)       = make_float2(c[mt][nt][0] + b0, c[mt][nt][1] + b1);
            *(float2*)(C + (size_t)(row + 8) * ldc + col) = make_float2(c[mt][nt][2] + b0, c[mt][nt][3] + b1);
        }
}

// ---------------------------------------------------------------------------
// Scores: S[z][m][n] = (Q_h[m].K_hkv[n])*SCALE + (1-mask[n])*-1e9
// ---------------------------------------------------------------------------
__global__ __launch_bounds__(256) void attn_scores_mma(
    const float* __restrict__ mask, const float* __restrict__ qkv)
{
    const int z = blockIdx.z, b = z / HH, h = z % HH, hkv = h % HKV;
    const int m0 = blockIdx.y * 128, n0 = blockIdx.x * 128;
    const float* A = qkv + (size_t)(b * NN + m0) * QKVW + h * HD;
    const float* B = qkv + (size_t)(b * NN + n0) * QKVW + KOFF + hkv * HD;
    float* C = g_S + (size_t)z * NN * NN;

    float c[2][8][4];
    #pragma unroll
    for (int mt = 0; mt < 2; ++mt)
        #pragma unroll
        for (int nt = 0; nt < 8; ++nt)
            #pragma unroll
            for (int i = 0; i < 4; ++i) c[mt][nt][i] = 0.f;

    mma_mainloop(A, QKVW, B, QKVW, HD, c);

    const int lane = threadIdx.x & 31, warp = threadIdx.x >> 5;
    const int rb = m0 + (warp >> 1) * 32 + (lane >> 2);
    const int cb = n0 + (warp & 1) * 64 + (lane & 3) * 2;
    #pragma unroll
    for (int mt = 0; mt < 2; ++mt)
        #pragma unroll
        for (int nt = 0; nt < 8; ++nt) {
            int row = rb + mt * 16, col = cb + nt * 8;
            float mb0 = (1.0f - mask[b * NN + col]) * -1e9f;
            float mb1 = (1.0f - mask[b * NN + col + 1]) * -1e9f;
            *(float2*)(C + (size_t)row * NN + col) =
                make_float2(c[mt][nt][0] * SCALE + mb0, c[mt][nt][1] * SCALE + mb1);
            *(float2*)(C + (size_t)(row + 8) * NN + col) =
                make_float2(c[mt][nt][2] * SCALE + mb0, c[mt][nt][3] * SCALE + mb1);
        }
}

// ---------------------------------------------------------------------------
// PV: ctx[b][m][h*HD+d] = sum_n P[z][m][n] * Vt[b][hkv][d][n]
// ---------------------------------------------------------------------------
__global__ __launch_bounds__(256) void attn_pv_mma()
{
    const int z = blockIdx.z, b = z / HH, h = z % HH, hkv = h % HKV;
    const int m0 = blockIdx.y * 128;
    const float* A = g_S + (size_t)z * NN * NN + (size_t)m0 * NN;
    const float* B = g_Vt + (size_t)(b * HKV + hkv) * HD * NN;

    float c[2][8][4];
    #pragma unroll
    for (int mt = 0; mt < 2; ++mt)
        #pragma unroll
        for (int nt = 0; nt < 8; ++nt)
            #pragma unroll
            for (int i = 0; i < 4; ++i) c[mt][nt][i] = 0.f;

    mma_mainloop(A, NN, B, NN, NN, c);

    const int lane = threadIdx.x & 31, warp = threadIdx.x >> 5;
    const int rb = (warp >> 1) * 32 + (lane >> 2);
    const int cb = (warp & 1) * 64 + (lane & 3) * 2;
    #pragma unroll
    for (int mt = 0; mt < 2; ++mt)
        #pragma unroll
        for (int nt = 0; nt < 8; ++nt) {
            int row = rb + mt * 16, col = cb + nt * 8;
            float* p0 = g_ctx + (size_t)(b * NN + m0 + row) * (HH * HD) + h * HD + col;
            float* p1 = g_ctx + (size_t)(b * NN + m0 + row + 8) * (HH * HD) + h * HD + col;
            *(float2*)p0 = make_float2(c[mt][nt][0], c[mt][nt][1]);
            *(float2*)p1 = make_float2(c[mt][nt][2], c[mt][nt][3]);
        }
}

// ---------------------------------------------------------------------------
// Transposes
// ---------------------------------------------------------------------------
__global__ void transpose_f32(const float* __restrict__ src, float* __restrict__ dst,
                              int R, int C)   // dst[c*R + r] = src[r*C + c]
{
    __shared__ float tile[32][33];
    int c0 = blockIdx.x * 32, r0 = blockIdx.y * 32;
    int tx = threadIdx.x, ty = threadIdx.y;
    #pragma unroll
    for (int i = ty; i < 32; i += 8)
        tile[i][tx] = src[(size_t)(r0 + i) * C + c0 + tx];
    __syncthreads();
    #pragma unroll
    for (int i = ty; i < 32; i += 8)
        dst[(size_t)(c0 + i) * R + r0 + tx] = tile[tx][i];
}

__global__ void transpose_v(const float* __restrict__ qkv)
{
    __shared__ float tile[32][33];
    int z = blockIdx.z, b = z / HKV, hkv = z % HKV;
    int n0 = blockIdx.x * 32, d0 = blockIdx.y * 32;
    int tx = threadIdx.x, ty = threadIdx.y;
    #pragma unroll
    for (int i = ty; i < 32; i += 8)
        tile[i][tx] = qkv[(size_t)(b * NN + n0 + i) * QKVW + VOFF + hkv * HD + d0 + tx];
    __syncthreads();
    float* dst = g_Vt + (size_t)(b * HKV + hkv) * HD * NN;
    #pragma unroll
    for (int i = ty; i < 32; i += 8)
        dst[(size_t)(d0 + i) * NN + n0 + tx] = tile[tx][i];
}

// ---------------------------------------------------------------------------
// RoPE in-place on g_QKV (Q and K parts). cos/sin: [N,64]
// ---------------------------------------------------------------------------
__global__ void rope_kernel(const float* __restrict__ cosb,
                            const float* __restrict__ sinb,
                            float* __restrict__ qkv)
{
    int idx = blockIdx.x * blockDim.x + threadIdx.x;
    const int NQ = BB * NN * HH * (HD / 2);
    const int NK = BB * NN * HKV * (HD / 2);
    if (idx < NQ) {
        int i  = idx & 63;
        int h  = (idx >> 6) % HH;
        int bn = idx / (64 * HH);
        int n  = bn % NN;
        float c = cosb[n * 64 + i], s = sinb[n * 64 + i];
        float* q = qkv + (size_t)bn * QKVW + h * HD;
        float t1 = q[i], t2 = q[i + 64];
        q[i]      = t1 * c + t2 * s;
        q[i + 64] = t2 * c - t1 * s;
    } else {
        idx -= NQ;
        if (idx < NK) {
            int i  = idx & 63;
            int hk = (idx >> 6) % HKV;
            int bn = idx / (64 * HKV);
            int n  = bn % NN;
            float c = cosb[n * 64 + i], s = sinb[n * 64 + i];
            float* k = qkv + (size_t)bn * QKVW + KOFF + hk * HD;
            float t1 = k[i], t2 = k[i + 64];
            k[i]      = t1 * c + t2 * s;
            k[i + 64] = t2 * c - t1 * s;
        }
    }
}

// ---------------------------------------------------------------------------
// Row softmax in-place on g_S
// ---------------------------------------------------------------------------
__global__ __launch_bounds__(256) void softmax_rows()
{
    __shared__ float red[256];
    float* p = g_S + (size_t)blockIdx.x * NN;
    const int t = threadIdx.x;

    float v[8];
    float m = -INFINITY;
    #pragma unroll
    for (int i = 0; i < 8; i++) { v[i] = p[t + i * 256]; m = fmaxf(m, v[i]); }
    red[t] = m; __syncthreads();
    for (int s = 128; s > 0; s >>= 1) {
        if (t < s) red[t] = fmaxf(red[t], red[t + s]);
        __syncthreads();
    }
    m = red[0]; __syncthreads();

    float sum = 0.f;
    #pragma unroll
    for (int i = 0; i < 8; i++) { v[i] = expf(v[i] - m); sum += v[i]; }
    red[t] = sum; __syncthreads();
    for (int s = 128; s > 0; s >>= 1) {
        if (t < s) red[t] += red[t + s];
        __syncthreads();
    }
    float inv = 1.0f / red[0];
    #pragma unroll
    for (int i = 0; i < 8; i++) p[t + i * 256] = v[i] * inv;
}

// ---------------------------------------------------------------------------
// Launch
// ---------------------------------------------------------------------------
extern "C" void kernel_launch(void* const* d_in, const int* in_sizes, int n_in,
                              void* d_out, int out_size)
{
    (void)in_sizes; (void)n_in; (void)out_size;

    const float* x    = (const float*)d_in[0];
    const float* cosb = (const float*)d_in[1];
    const float* sinb = (const float*)d_in[2];
    const float* mask = (const float*)d_in[3];
    const float* Wq   = (const float*)d_in[4];
    const float* Wkv  = (const float*)d_in[5];
    const float* Wo   = (const float*)d_in[6];
    const float* bo   = (const float*)d_in[7];
    float* out = (float*)d_out;

    float *pQKV, *pWT, *pWoT, *pCtx;
    cudaGetSymbolAddress((void**)&pQKV, g_QKV);
    cudaGetSymbolAddress((void**)&pWT,  g_WT);
    cudaGetSymbolAddress((void**)&pWoT, g_WoT);
    cudaGetSymbolAddress((void**)&pCtx, g_ctx);

    const int M = BB * NN;   // 4096
    dim3 tb(32, 8);

    // Weight transposes: WT[j][k] = [Wq|Wkv][k][j], WoT[j][k] = Wo[k][j]
    transpose_f32<<<dim3(DD / 32, DD / 32), tb>>>(Wq, pWT, DD, DD);
    transpose_f32<<<dim3((2 * HKV * HD) / 32, DD / 32), tb>>>(Wkv, pWT + (size_t)KOFF * DD, DD, 2 * HKV * HD);
    transpose_f32<<<dim3(DD / 32, DD / 32), tb>>>(Wo, pWoT, DD, DD);

    // QKV = x @ [Wq|Wkv]^T(transposed weights) : [4096,2048] x [3072,2048]
    gemm_nt_mma<<<dim3(QKVW / 128, M / 128), 256>>>(x, DD, pWT, DD, pQKV, QKVW, DD, nullptr);

    // RoPE
    {
        int total = BB * NN * HH * (HD / 2) + BB * NN * HKV * (HD / 2);
        rope_kernel<<<(total + 255) / 256, 256>>>(cosb, sinb, pQKV);
    }

    // S = Q K^T * scale + maskbias
    attn_scores_mma<<<dim3(NN / 128, NN / 128, BB * HH), 256>>>(mask, pQKV);

    // V transpose for NT PV
    transpose_v<<<dim3(NN / 32, HD / 32, BB * HKV), tb>>>(pQKV);

    // softmax
    softmax_rows<<<BB * HH * NN, 256>>>();

    // ctx = P V
    attn_pv_mma<<<dim3(1, NN / 128, BB * HH), 256>>>();

    // out = ctx @ Wo + bo
    gemm_nt_mma<<<dim3(DD / 128, M / 128), 256>>>(pCtx, HH * HD, pWoT, DD, out, DD, DD, bo);
}